// round 15
// baseline (speedup 1.0000x reference)
#include <cuda_runtime.h>
#include <cuda_bf16.h>
#include <math.h>
#include <stdint.h>

#define NN 50000
#define EE 400000
#define ET 450000      // EE + NN self loops
#define LN_EPS 1e-5f

// ---------------- scratch (device globals; allocation is forbidden) ----------
__device__ float g_h[(size_t)NN * 512];
__device__ float g_feat[(size_t)NN * 512];
__device__ float g_ssrc[NN * 4];
__device__ float g_sdst[NN * 4];
__device__ float g_den[NN * 4];
__device__ float g_alpha[(size_t)ET * 4];
__device__ int   g_cnt[NN];
__device__ int   g_off[NN + 1];
__device__ int   g_pos[NN];
__device__ int   g_srcs[ET];

// ---------------- bf16x3 helpers ----------------------------------------------
__device__ __forceinline__ uint32_t pack_hi(float x, float y, float& lx, float& ly) {
    __nv_bfloat16 hx = __float2bfloat16_rn(x);
    __nv_bfloat16 hy = __float2bfloat16_rn(y);
    lx = x - __bfloat162float(hx);
    ly = y - __bfloat162float(hy);
    __nv_bfloat162 p = __halves2bfloat162(hx, hy);
    return *(uint32_t*)&p;
}
__device__ __forceinline__ uint32_t pack_lo(float lx, float ly) {
    __nv_bfloat162 p = __halves2bfloat162(__float2bfloat16_rn(lx),
                                          __float2bfloat16_rn(ly));
    return *(uint32_t*)&p;
}
__device__ __forceinline__ void mma_bf16(float* c, const uint32_t* a, const uint32_t* b) {
    asm volatile(
        "mma.sync.aligned.m16n8k16.row.col.f32.bf16.bf16.f32 "
        "{%0,%1,%2,%3}, {%4,%5,%6,%7}, {%8,%9}, {%0,%1,%2,%3};"
        : "+f"(c[0]), "+f"(c[1]), "+f"(c[2]), "+f"(c[3])
        : "r"(a[0]), "r"(a[1]), "r"(a[2]), "r"(a[3]), "r"(b[0]), "r"(b[1]));
}

// ---------------- bf16x3 GEMM, 128x64 tile + fused GAT scores -----------------
// __launch_bounds__(256, 2): cap regs at 128 -> 2 CTAs/SM for latency cover.
__global__ __launch_bounds__(256, 2) void gemm_bf16x3(
        const float* __restrict__ A, const float* __restrict__ B,
        float* __restrict__ C, int M, int N, int K,
        float* ssrc, float* sdst, const float* __restrict__ asrc,
        const float* __restrict__ adst, int H, int shiftC) {
    __shared__ uint32_t Ahi[2][8][136], Alo[2][8][136];
    __shared__ uint32_t Bhi[2][8][72],  Blo[2][8][72];

    int tid = threadIdx.x;
    int lane = tid & 31, wid = tid >> 5;
    int wm = (wid >> 1) * 32;
    int wn = (wid & 1) * 32;
    int q = lane & 3, t4 = lane >> 2;
    int row0 = blockIdx.y * 128, col0 = blockIdx.x * 64;

    int a_r = tid >> 2, a_k2 = (tid & 3) * 2;
    int b_k2 = tid >> 5, b_n = lane * 2;

    float4 pa[2];
    float2 pb0, pb1;

    auto prefetch = [&](int k0) {
#pragma unroll
        for (int i = 0; i < 2; i++) {
            int r = row0 + a_r + i * 64;
            if (r < M) pa[i] = *(const float4*)(A + (size_t)r * K + k0 + a_k2 * 2);
            else       pa[i] = make_float4(0.f, 0.f, 0.f, 0.f);
        }
        const float* bp = B + (size_t)(k0 + b_k2 * 2) * N + col0 + b_n;
        pb0 = *(const float2*)bp;
        pb1 = *(const float2*)(bp + N);
    };

    auto convert_store = [&](int buf) {
#pragma unroll
        for (int i = 0; i < 2; i++) {
            int r = a_r + i * 64;
            float lx, ly, lz, lw;
            uint32_t h0 = pack_hi(pa[i].x, pa[i].y, lx, ly);
            uint32_t h1 = pack_hi(pa[i].z, pa[i].w, lz, lw);
            Ahi[buf][a_k2][r]     = h0;
            Ahi[buf][a_k2 + 1][r] = h1;
            Alo[buf][a_k2][r]     = pack_lo(lx, ly);
            Alo[buf][a_k2 + 1][r] = pack_lo(lz, lw);
        }
        {
            float l00, l10, l01, l11;
            uint32_t h0 = pack_hi(pb0.x, pb1.x, l00, l10);
            uint32_t h1 = pack_hi(pb0.y, pb1.y, l01, l11);
            Bhi[buf][b_k2][b_n]     = h0;
            Bhi[buf][b_k2][b_n + 1] = h1;
            Blo[buf][b_k2][b_n]     = pack_lo(l00, l10);
            Blo[buf][b_k2][b_n + 1] = pack_lo(l01, l11);
        }
    };

    float acc[2][4][4];
#pragma unroll
    for (int i = 0; i < 2; i++)
#pragma unroll
        for (int j = 0; j < 4; j++)
#pragma unroll
            for (int k = 0; k < 4; k++) acc[i][j][k] = 0.f;

    int ntiles = K >> 4;
    prefetch(0);
    convert_store(0);
    __syncthreads();

    int buf = 0;
    for (int t = 0; t < ntiles; t++) {
        if (t + 1 < ntiles) prefetch((t + 1) << 4);

        uint32_t ah[2][4], al[2][4], bh[4][2], bl[4][2];
#pragma unroll
        for (int mt = 0; mt < 2; mt++) {
            int m0 = wm + mt * 16 + t4;
            ah[mt][0] = Ahi[buf][q][m0];     ah[mt][1] = Ahi[buf][q][m0 + 8];
            ah[mt][2] = Ahi[buf][q + 4][m0]; ah[mt][3] = Ahi[buf][q + 4][m0 + 8];
            al[mt][0] = Alo[buf][q][m0];     al[mt][1] = Alo[buf][q][m0 + 8];
            al[mt][2] = Alo[buf][q + 4][m0]; al[mt][3] = Alo[buf][q + 4][m0 + 8];
        }
#pragma unroll
        for (int nt = 0; nt < 4; nt++) {
            int n0 = wn + nt * 8 + t4;
            bh[nt][0] = Bhi[buf][q][n0]; bh[nt][1] = Bhi[buf][q + 4][n0];
            bl[nt][0] = Blo[buf][q][n0]; bl[nt][1] = Blo[buf][q + 4][n0];
        }
#pragma unroll
        for (int mt = 0; mt < 2; mt++)
#pragma unroll
            for (int nt = 0; nt < 4; nt++) {
                mma_bf16(acc[mt][nt], ah[mt], bh[nt]);
                mma_bf16(acc[mt][nt], ah[mt], bl[nt]);
                mma_bf16(acc[mt][nt], al[mt], bh[nt]);
            }

        if (t + 1 < ntiles) convert_store(buf ^ 1);
        __syncthreads();
        buf ^= 1;
    }

#pragma unroll
    for (int mt = 0; mt < 2; mt++) {
        int r0 = row0 + wm + mt * 16 + t4;
#pragma unroll
        for (int nt = 0; nt < 4; nt++) {
            int cc = col0 + wn + nt * 8 + q * 2;
            if (r0 < M) {
                C[(size_t)r0 * N + cc]     = acc[mt][nt][0];
                C[(size_t)r0 * N + cc + 1] = acc[mt][nt][1];
            }
            if (r0 + 8 < M) {
                C[(size_t)(r0 + 8) * N + cc]     = acc[mt][nt][2];
                C[(size_t)(r0 + 8) * N + cc + 1] = acc[mt][nt][3];
            }
        }
    }

    // fused GAT scores: each warp's 32-col span lies inside one head
    if (asrc) {
        int Cm1 = (1 << shiftC) - 1;
        int hd = (col0 + wn) >> shiftC;
        float av_s[4][2], av_d[4][2];
#pragma unroll
        for (int nt = 0; nt < 4; nt++)
#pragma unroll
            for (int k = 0; k < 2; k++) {
                int ci = (col0 + wn + nt * 8 + q * 2 + k) & Cm1;
                av_s[nt][k] = asrc[(hd << shiftC) + ci];
                av_d[nt][k] = adst[(hd << shiftC) + ci];
            }
#pragma unroll
        for (int mt = 0; mt < 2; mt++) {
            float s0 = 0.f, s1 = 0.f, d0 = 0.f, d1 = 0.f;
#pragma unroll
            for (int nt = 0; nt < 4; nt++) {
                s0 += acc[mt][nt][0] * av_s[nt][0] + acc[mt][nt][1] * av_s[nt][1];
                s1 += acc[mt][nt][2] * av_s[nt][0] + acc[mt][nt][3] * av_s[nt][1];
                d0 += acc[mt][nt][0] * av_d[nt][0] + acc[mt][nt][1] * av_d[nt][1];
                d1 += acc[mt][nt][2] * av_d[nt][0] + acc[mt][nt][3] * av_d[nt][1];
            }
#pragma unroll
            for (int o = 1; o < 4; o <<= 1) {
                s0 += __shfl_xor_sync(0xffffffffu, s0, o);
                s1 += __shfl_xor_sync(0xffffffffu, s1, o);
                d0 += __shfl_xor_sync(0xffffffffu, d0, o);
                d1 += __shfl_xor_sync(0xffffffffu, d1, o);
            }
            if (q == 0) {
                int r0 = row0 + wm + mt * 16 + t4;
                if (r0 < M) {
                    atomicAdd(&ssrc[r0 * H + hd], s0);
                    atomicAdd(&sdst[r0 * H + hd], d0);
                }
                if (r0 + 8 < M) {
                    atomicAdd(&ssrc[(r0 + 8) * H + hd], s1);
                    atomicAdd(&sdst[(r0 + 8) * H + hd], d1);
                }
            }
        }
    }
}

// ---------------- CSR construction -------------------------------------------
__global__ void zero_k(int* __restrict__ cnt, int* __restrict__ pos) {
    int i = blockIdx.x * blockDim.x + threadIdx.x;
    if (i < NN) { cnt[i] = 0; pos[i] = 0; }
}
__global__ void hist_k(const int* __restrict__ ei, int* __restrict__ cnt) {
    int e = blockIdx.x * blockDim.x + threadIdx.x;
    if (e < EE) atomicAdd(&cnt[ei[EE + e]], 1);
}
__global__ void scan_k(const int* __restrict__ cnt, int* __restrict__ off) {
    __shared__ int wsum[32];
    __shared__ int carry_s;
    int t = threadIdx.x, lane = t & 31, w = t >> 5;
    if (t == 0) carry_s = 0;
    __syncthreads();
    for (int base = 0; base < NN; base += 1024) {
        int i = base + t;
        int x = (i < NN) ? cnt[i] + 1 : 0;
#pragma unroll
        for (int o = 1; o < 32; o <<= 1) {
            int y = __shfl_up_sync(0xffffffffu, x, o);
            if (lane >= o) x += y;
        }
        if (lane == 31) wsum[w] = x;
        __syncthreads();
        if (w == 0) {
            int s = wsum[lane];
#pragma unroll
            for (int o = 1; o < 32; o <<= 1) {
                int y = __shfl_up_sync(0xffffffffu, s, o);
                if (lane >= o) s += y;
            }
            wsum[lane] = s;
        }
        __syncthreads();
        int woff = (w == 0) ? 0 : wsum[w - 1];
        int total = wsum[31];
        if (i < NN) off[i + 1] = carry_s + woff + x;
        __syncthreads();
        if (t == 0) carry_s += total;
        __syncthreads();
    }
    if (threadIdx.x == 0) off[0] = 0;
}
__global__ void scatter_k(const int* __restrict__ ei, const int* __restrict__ off,
                          int* __restrict__ pos, int* __restrict__ srcs) {
    int e = blockIdx.x * blockDim.x + threadIdx.x;
    if (e >= ET) return;
    int s, d;
    if (e < EE) { s = ei[e]; d = ei[EE + e]; }
    else        { s = e - EE; d = s; }
    int p = atomicAdd(&pos[d], 1);
    srcs[off[d] + p] = s;
}

// ---------------- zero score accumulators -------------------------------------
__global__ void zs_k(float* __restrict__ a, float* __restrict__ b, int n) {
    int i = blockIdx.x * blockDim.x + threadIdx.x;
    if (i < n) { a[i] = 0.f; b[i] = 0.f; }
}

// ---------------- load H scores as a vector -----------------------------------
template<int H>
__device__ __forceinline__ void load_sv(const float* __restrict__ p, int n, float* out) {
    if (H == 4) { float4 v = *(const float4*)(p + n * 4);
                  out[0] = v.x; out[1] = v.y; out[2] = v.z; out[3] = v.w; }
    else if (H == 2) { float2 v = *(const float2*)(p + n * 2);
                       out[0] = v.x; out[1] = v.y; }
    else out[0] = p[n];
}

// ---------------- alpha: warp per dst node, SINGLE pass (no max shift) --------
template<int H>
__global__ void alpha_k(const int* __restrict__ off, const int* __restrict__ srcs,
                        const float* __restrict__ ssrc, const float* __restrict__ sdst,
                        float* __restrict__ alpha, float* __restrict__ den) {
    int n = (blockIdx.x * blockDim.x + threadIdx.x) >> 5;
    int lane = threadIdx.x & 31;
    if (n >= NN) return;
    int beg = off[n], end = off[n + 1];
    float sdn[H];
    load_sv<H>(sdst, n, sdn);

    float dn[H];
#pragma unroll
    for (int hd = 0; hd < H; hd++) dn[hd] = 0.f;
    for (int j = beg + lane; j < end; j += 32) {
        int s = srcs[j];
        float sv[H], ev[H];
        load_sv<H>(ssrc, s, sv);
#pragma unroll
        for (int hd = 0; hd < H; hd++) {
            float v = sv[hd] + sdn[hd];
            v = v > 0.f ? v : 0.2f * v;
            ev[hd] = expf(v);
            dn[hd] += ev[hd];
        }
        if (H == 4)      *(float4*)(alpha + (size_t)j * 4) = make_float4(ev[0], ev[1], ev[2], ev[3]);
        else if (H == 2) *(float2*)(alpha + (size_t)j * 2) = make_float2(ev[0], ev[1]);
        else             alpha[j] = ev[0];
    }
#pragma unroll
    for (int o = 16; o; o >>= 1)
#pragma unroll
        for (int hd = 0; hd < H; hd++)
            dn[hd] += __shfl_xor_sync(0xffffffffu, dn[hd], o);
    if (lane == 0) {
        if (H == 4)      *(float4*)(den + n * 4) = make_float4(dn[0], dn[1], dn[2], dn[3]);
        else if (H == 2) *(float2*)(den + n * 2) = make_float2(dn[0], dn[1]);
        else             den[n] = dn[0];
    }
}

// ---------------- fused gather-aggregate + /den + bias + LN + ELU -------------
#define AG_CHUNK 16
template<int H, int G, int SHIFT>
__global__ __launch_bounds__(128) void gat_agg_k(
        const int* __restrict__ off, const int* __restrict__ srcs,
        const float* __restrict__ alpha, const float* __restrict__ den,
        const float* __restrict__ h,
        const float* __restrict__ bias, const float* __restrict__ lng,
        const float* __restrict__ lnb, float* __restrict__ out) {
    const int NPB = 128 / G;
    const int HC = G * 4;
    __shared__ float s_alpha[NPB][AG_CHUNK][H];
    __shared__ int   s_src[NPB][AG_CHUNK];
    __shared__ float red[256];

    int t = threadIdx.x;
    int grp = t / G, g = t % G;
    int n = blockIdx.x * NPB + grp;

    int beg = off[n], end = off[n + 1];
    int c0 = g * 4;
    const int hd0 = (G * 4 == (1 << SHIFT)) ? 0 : -1;
    int myhd = (hd0 == 0) ? 0 : (c0 >> SHIFT);
    float inv_den = 1.f / den[n * H + myhd];
    float4 acc = make_float4(0.f, 0.f, 0.f, 0.f);

    for (int it = 0;; it++) {
        int cb = beg + it * AG_CHUNK;
        bool active = cb < end;
        if (!__syncthreads_or(active)) break;
        int clen = active ? min(AG_CHUNK, end - cb) : 0;
        if (g < clen) {
            s_src[grp][g] = srcs[cb + g];
            float av[H];
            load_sv<H>(alpha, cb + g, av);
#pragma unroll
            for (int hd = 0; hd < H; hd++) s_alpha[grp][g][hd] = av[hd];
        }
        __syncthreads();
        int k = 0;
        for (; k + 8 <= clen; k += 8) {
            int   si[8];
            float ai[8];
            float4 vi[8];
#pragma unroll
            for (int u = 0; u < 8; u++) {
                si[u] = s_src[grp][k + u];
                ai[u] = s_alpha[grp][k + u][myhd];
            }
#pragma unroll
            for (int u = 0; u < 8; u++)
                vi[u] = *(const float4*)(h + (size_t)si[u] * HC + c0);
#pragma unroll
            for (int u = 0; u < 8; u++) {
                acc.x += ai[u] * vi[u].x; acc.y += ai[u] * vi[u].y;
                acc.z += ai[u] * vi[u].z; acc.w += ai[u] * vi[u].w;
            }
        }
        for (; k + 4 <= clen; k += 4) {
            int s0 = s_src[grp][k],     s1 = s_src[grp][k + 1];
            int s2 = s_src[grp][k + 2], s3 = s_src[grp][k + 3];
            float a0 = s_alpha[grp][k][myhd],     a1 = s_alpha[grp][k + 1][myhd];
            float a2 = s_alpha[grp][k + 2][myhd], a3 = s_alpha[grp][k + 3][myhd];
            float4 v0 = *(const float4*)(h + (size_t)s0 * HC + c0);
            float4 v1 = *(const float4*)(h + (size_t)s1 * HC + c0);
            float4 v2 = *(const float4*)(h + (size_t)s2 * HC + c0);
            float4 v3 = *(const float4*)(h + (size_t)s3 * HC + c0);
            acc.x += a0 * v0.x; acc.y += a0 * v0.y; acc.z += a0 * v0.z; acc.w += a0 * v0.w;
            acc.x += a1 * v1.x; acc.y += a1 * v1.y; acc.z += a1 * v1.z; acc.w += a1 * v1.w;
            acc.x += a2 * v2.x; acc.y += a2 * v2.y; acc.z += a2 * v2.z; acc.w += a2 * v2.w;
            acc.x += a3 * v3.x; acc.y += a3 * v3.y; acc.z += a3 * v3.z; acc.w += a3 * v3.w;
        }
        for (; k < clen; k++) {
            float a = s_alpha[grp][k][myhd];
            float4 hv = *(const float4*)(h + (size_t)s_src[grp][k] * HC + c0);
            acc.x += a * hv.x; acc.y += a * hv.y;
            acc.z += a * hv.z; acc.w += a * hv.w;
        }
    }

    float4 b4 = *(const float4*)(bias + c0);
    float4 val;
    val.x = acc.x * inv_den + b4.x; val.y = acc.y * inv_den + b4.y;
    val.z = acc.z * inv_den + b4.z; val.w = acc.w * inv_den + b4.w;
    float sum = val.x + val.y + val.z + val.w;
    float sq  = val.x * val.x + val.y * val.y + val.z * val.z + val.w * val.w;
    red[t] = sum; red[128 + t] = sq;
    __syncthreads();
#pragma unroll
    for (int o = G >> 1; o; o >>= 1) {
        if (g < o) { red[t] += red[t + o]; red[128 + t] += red[128 + t + o]; }
        __syncthreads();
    }
    int gb = grp * G;
    float mu = red[gb] / HC;
    float var = red[128 + gb] / HC - mu * mu;
    float rstd = rsqrtf(var + LN_EPS);
    float4 g4 = *(const float4*)(lng + c0);
    float4 o4 = *(const float4*)(lnb + c0);
    float y0 = (val.x - mu) * rstd * g4.x + o4.x;
    float y1 = (val.y - mu) * rstd * g4.y + o4.y;
    float y2 = (val.z - mu) * rstd * g4.z + o4.z;
    float y3 = (val.w - mu) * rstd * g4.w + o4.w;
    float4 r;
    r.x = y0 > 0.f ? y0 : expm1f(y0);
    r.y = y1 > 0.f ? y1 : expm1f(y1);
    r.z = y2 > 0.f ? y2 : expm1f(y2);
    r.w = y3 > 0.f ? y3 : expm1f(y3);
    *(float4*)(out + (size_t)n * HC + c0) = r;
}

// ---------------- decoder epilogue: +bias -> LN -> ELU -----------------------
__global__ void ln_elu_k(const float* __restrict__ in, const float* __restrict__ bias,
                         const float* __restrict__ lng, const float* __restrict__ lnb,
                         float* __restrict__ out, int W) {
    __shared__ float sh[256];
    int n = blockIdx.x;
    int t = threadIdx.x;
    float v[4];
    float sum = 0.f, sq = 0.f;
    int cnt = 0;
    for (int c = t; c < W; c += 128) {
        float val = in[(size_t)n * W + c] + bias[c];
        v[cnt++] = val; sum += val; sq += val * val;
    }
    sh[t] = sum; sh[128 + t] = sq;
    __syncthreads();
    for (int o = 64; o; o >>= 1) {
        if (t < o) { sh[t] += sh[t + o]; sh[128 + t] += sh[128 + t + o]; }
        __syncthreads();
    }
    float mu = sh[0] / W;
    float var = sh[128] / W - mu * mu;
    float rstd = rsqrtf(var + LN_EPS);
    cnt = 0;
    for (int c = t; c < W; c += 128) {
        float y = (v[cnt++] - mu) * rstd * lng[c] + lnb[c];
        out[(size_t)n * W + c] = y > 0.f ? y : expm1f(y);
    }
}

// ---------------- host orchestration -----------------------------------------
extern "C" void kernel_launch(void* const* d_in, const int* in_sizes, int n_in,
                              void* d_out, int out_size) {
    const float* x   = (const float*)d_in[0];
    const int*   ei  = (const int*)d_in[1];
    const float* W1  = (const float*)d_in[2];
    const float* a1s = (const float*)d_in[3];
    const float* a1d = (const float*)d_in[4];
    const float* b1  = (const float*)d_in[5];
    const float* g1  = (const float*)d_in[6];
    const float* bb1 = (const float*)d_in[7];
    const float* W2  = (const float*)d_in[8];
    const float* a2s = (const float*)d_in[9];
    const float* a2d = (const float*)d_in[10];
    const float* b2  = (const float*)d_in[11];
    const float* g2  = (const float*)d_in[12];
    const float* bb2 = (const float*)d_in[13];
    const float* W3  = (const float*)d_in[14];
    const float* a3s = (const float*)d_in[15];
    const float* a3d = (const float*)d_in[16];
    const float* b3  = (const float*)d_in[17];
    const float* g3  = (const float*)d_in[18];
    const float* bb3 = (const float*)d_in[19];
    const float* dW1   = (const float*)d_in[20];
    const float* db1   = (const float*)d_in[21];
    const float* lnd1g = (const float*)d_in[22];
    const float* lnd1b = (const float*)d_in[23];
    const float* dW2   = (const float*)d_in[24];
    const float* db2   = (const float*)d_in[25];
    const float* lnd2g = (const float*)d_in[26];
    const float* lnd2b = (const float*)d_in[27];

    float *h, *feat, *ssrc, *sdst, *den, *alpha;
    int *cnt, *off, *pos, *srcs;
    cudaGetSymbolAddress((void**)&h,     g_h);
    cudaGetSymbolAddress((void**)&feat,  g_feat);
    cudaGetSymbolAddress((void**)&ssrc,  g_ssrc);
    cudaGetSymbolAddress((void**)&sdst,  g_sdst);
    cudaGetSymbolAddress((void**)&den,   g_den);
    cudaGetSymbolAddress((void**)&alpha, g_alpha);
    cudaGetSymbolAddress((void**)&cnt,   g_cnt);
    cudaGetSymbolAddress((void**)&off,   g_off);
    cudaGetSymbolAddress((void**)&pos,   g_pos);
    cudaGetSymbolAddress((void**)&srcs,  g_srcs);

    // side stream + events (created once; never destroyed -> capture-safe)
    static cudaStream_t s2 = nullptr;
    static cudaEvent_t ev_fork = nullptr, ev_join = nullptr;
    if (!s2) {
        cudaStreamCreateWithFlags(&s2, cudaStreamNonBlocking);
        cudaEventCreateWithFlags(&ev_fork, cudaEventDisableTiming);
        cudaEventCreateWithFlags(&ev_join, cudaEventDisableTiming);
    }

    // ---- fork: CSR build on s2, overlapped with layer-1 zs+GEMM on main ----
    cudaEventRecord(ev_fork, 0);
    cudaStreamWaitEvent(s2, ev_fork, 0);
    zero_k<<<(NN + 255) / 256, 256, 0, s2>>>(cnt, pos);
    hist_k<<<(EE + 255) / 256, 256, 0, s2>>>(ei, cnt);
    scan_k<<<1, 1024, 0, s2>>>(cnt, off);
    scatter_k<<<(ET + 255) / 256, 256, 0, s2>>>(ei, off, pos, srcs);
    cudaEventRecord(ev_join, s2);

    const int MB = (NN + 127) / 128;
    auto run_gemm = [&](const float* A, const float* B, float* C, int N, int K,
                        const float* as_, const float* ad_, int H, int shiftC) {
        gemm_bf16x3<<<dim3(N / 64, MB), 256>>>(A, B, C, NN, N, K,
                                               ssrc, sdst, as_, ad_, H, shiftC);
    };

    // ---- layer 1: H=4, C=128, HC=512, G=128, NPB=1 ----
    zs_k<<<(NN * 4 + 255) / 256, 256>>>(ssrc, sdst, NN * 4);
    run_gemm(x, W1, h, 512, 128, a1s, a1d, 4, 7);
    cudaStreamWaitEvent(0, ev_join, 0);   // join: alpha needs the CSR
    alpha_k<4><<<(NN * 32 + 255) / 256, 256>>>(off, srcs, ssrc, sdst, alpha, den);
    gat_agg_k<4, 128, 7><<<NN, 128>>>(off, srcs, alpha, den, h, b1, g1, bb1, feat);

    // ---- layer 2: H=2, C=128, HC=256, G=64, NPB=2 ----
    zs_k<<<(NN * 2 + 255) / 256, 256>>>(ssrc, sdst, NN * 2);
    run_gemm(feat, W2, h, 256, 512, a2s, a2d, 2, 7);
    alpha_k<2><<<(NN * 32 + 255) / 256, 256>>>(off, srcs, ssrc, sdst, alpha, den);
    gat_agg_k<2, 64, 7><<<NN / 2, 128>>>(off, srcs, alpha, den, h, b2, g2, bb2, feat);

    // ---- layer 3: H=1, C=64, HC=64, G=16, NPB=8 ----
    zs_k<<<(NN + 255) / 256, 256>>>(ssrc, sdst, NN);
    run_gemm(feat, W3, h, 64, 256, a3s, a3d, 1, 6);
    alpha_k<1><<<(NN * 32 + 255) / 256, 256>>>(off, srcs, ssrc, sdst, alpha, den);
    gat_agg_k<1, 16, 6><<<NN / 8, 128>>>(off, srcs, alpha, den, h, b3, g3, bb3, feat);

    // ---- decoder ----
    run_gemm(feat, dW1, h, 128, 64, nullptr, nullptr, 1, 0);
    ln_elu_k<<<NN, 128>>>(h, db1, lnd1g, lnd1b, feat, 128);
    run_gemm(feat, dW2, h, 128, 128, nullptr, nullptr, 1, 0);
    ln_elu_k<<<NN, 128>>>(h, db2, lnd2g, lnd2b, (float*)d_out, 128);
}

// round 16
// speedup vs baseline: 1.0503x; 1.0503x over previous
#include <cuda_runtime.h>
#include <cuda_bf16.h>
#include <math.h>
#include <stdint.h>

#define NN 50000
#define EE 400000
#define ET 450000      // EE + NN self loops
#define LN_EPS 1e-5f

// ---------------- scratch (device globals; allocation is forbidden) ----------
__device__ float g_h[(size_t)NN * 512];
__device__ float g_feat[(size_t)NN * 512];
__device__ float g_ssrc[NN * 4];
__device__ float g_sdst[NN * 4];
__device__ float g_den[NN * 4];
__device__ float g_alpha[(size_t)ET * 4];
__device__ int   g_cnt[NN];
__device__ int   g_off[NN + 1];
__device__ int   g_pos[NN];
__device__ int   g_srcs[ET];

// ---------------- bf16x3 helpers ----------------------------------------------
__device__ __forceinline__ uint32_t pack_hi(float x, float y, float& lx, float& ly) {
    __nv_bfloat16 hx = __float2bfloat16_rn(x);
    __nv_bfloat16 hy = __float2bfloat16_rn(y);
    lx = x - __bfloat162float(hx);
    ly = y - __bfloat162float(hy);
    __nv_bfloat162 p = __halves2bfloat162(hx, hy);
    return *(uint32_t*)&p;
}
__device__ __forceinline__ uint32_t pack_lo(float lx, float ly) {
    __nv_bfloat162 p = __halves2bfloat162(__float2bfloat16_rn(lx),
                                          __float2bfloat16_rn(ly));
    return *(uint32_t*)&p;
}
__device__ __forceinline__ void mma_bf16(float* c, const uint32_t* a, const uint32_t* b) {
    asm volatile(
        "mma.sync.aligned.m16n8k16.row.col.f32.bf16.bf16.f32 "
        "{%0,%1,%2,%3}, {%4,%5,%6,%7}, {%8,%9}, {%0,%1,%2,%3};"
        : "+f"(c[0]), "+f"(c[1]), "+f"(c[2]), "+f"(c[3])
        : "r"(a[0]), "r"(a[1]), "r"(a[2]), "r"(a[3]), "r"(b[0]), "r"(b[1]));
}

// ---------------- bf16x3 GEMM, 128x64 tile + fused GAT scores -----------------
__global__ __launch_bounds__(256) void gemm_bf16x3(
        const float* __restrict__ A, const float* __restrict__ B,
        float* __restrict__ C, int M, int N, int K,
        float* ssrc, float* sdst, const float* __restrict__ asrc,
        const float* __restrict__ adst, int H, int shiftC) {
    __shared__ uint32_t Ahi[2][8][136], Alo[2][8][136];
    __shared__ uint32_t Bhi[2][8][72],  Blo[2][8][72];

    int tid = threadIdx.x;
    int lane = tid & 31, wid = tid >> 5;
    int wm = (wid >> 1) * 32;
    int wn = (wid & 1) * 32;
    int q = lane & 3, t4 = lane >> 2;
    int row0 = blockIdx.y * 128, col0 = blockIdx.x * 64;

    int a_r = tid >> 2, a_k2 = (tid & 3) * 2;
    int b_k2 = tid >> 5, b_n = lane * 2;

    float4 pa[2];
    float2 pb0, pb1;

    auto prefetch = [&](int k0) {
#pragma unroll
        for (int i = 0; i < 2; i++) {
            int r = row0 + a_r + i * 64;
            if (r < M) pa[i] = *(const float4*)(A + (size_t)r * K + k0 + a_k2 * 2);
            else       pa[i] = make_float4(0.f, 0.f, 0.f, 0.f);
        }
        const float* bp = B + (size_t)(k0 + b_k2 * 2) * N + col0 + b_n;
        pb0 = *(const float2*)bp;
        pb1 = *(const float2*)(bp + N);
    };

    auto convert_store = [&](int buf) {
#pragma unroll
        for (int i = 0; i < 2; i++) {
            int r = a_r + i * 64;
            float lx, ly, lz, lw;
            uint32_t h0 = pack_hi(pa[i].x, pa[i].y, lx, ly);
            uint32_t h1 = pack_hi(pa[i].z, pa[i].w, lz, lw);
            Ahi[buf][a_k2][r]     = h0;
            Ahi[buf][a_k2 + 1][r] = h1;
            Alo[buf][a_k2][r]     = pack_lo(lx, ly);
            Alo[buf][a_k2 + 1][r] = pack_lo(lz, lw);
        }
        {
            float l00, l10, l01, l11;
            uint32_t h0 = pack_hi(pb0.x, pb1.x, l00, l10);
            uint32_t h1 = pack_hi(pb0.y, pb1.y, l01, l11);
            Bhi[buf][b_k2][b_n]     = h0;
            Bhi[buf][b_k2][b_n + 1] = h1;
            Blo[buf][b_k2][b_n]     = pack_lo(l00, l10);
            Blo[buf][b_k2][b_n + 1] = pack_lo(l01, l11);
        }
    };

    float acc[2][4][4];
#pragma unroll
    for (int i = 0; i < 2; i++)
#pragma unroll
        for (int j = 0; j < 4; j++)
#pragma unroll
            for (int k = 0; k < 4; k++) acc[i][j][k] = 0.f;

    int ntiles = K >> 4;
    prefetch(0);
    convert_store(0);
    __syncthreads();

    int buf = 0;
    for (int t = 0; t < ntiles; t++) {
        if (t + 1 < ntiles) prefetch((t + 1) << 4);

        uint32_t ah[2][4], al[2][4], bh[4][2], bl[4][2];
#pragma unroll
        for (int mt = 0; mt < 2; mt++) {
            int m0 = wm + mt * 16 + t4;
            ah[mt][0] = Ahi[buf][q][m0];     ah[mt][1] = Ahi[buf][q][m0 + 8];
            ah[mt][2] = Ahi[buf][q + 4][m0]; ah[mt][3] = Ahi[buf][q + 4][m0 + 8];
            al[mt][0] = Alo[buf][q][m0];     al[mt][1] = Alo[buf][q][m0 + 8];
            al[mt][2] = Alo[buf][q + 4][m0]; al[mt][3] = Alo[buf][q + 4][m0 + 8];
        }
#pragma unroll
        for (int nt = 0; nt < 4; nt++) {
            int n0 = wn + nt * 8 + t4;
            bh[nt][0] = Bhi[buf][q][n0]; bh[nt][1] = Bhi[buf][q + 4][n0];
            bl[nt][0] = Blo[buf][q][n0]; bl[nt][1] = Blo[buf][q + 4][n0];
        }
#pragma unroll
        for (int mt = 0; mt < 2; mt++)
#pragma unroll
            for (int nt = 0; nt < 4; nt++) {
                mma_bf16(acc[mt][nt], ah[mt], bh[nt]);
                mma_bf16(acc[mt][nt], ah[mt], bl[nt]);
                mma_bf16(acc[mt][nt], al[mt], bh[nt]);
            }

        if (t + 1 < ntiles) convert_store(buf ^ 1);
        __syncthreads();
        buf ^= 1;
    }

#pragma unroll
    for (int mt = 0; mt < 2; mt++) {
        int r0 = row0 + wm + mt * 16 + t4;
#pragma unroll
        for (int nt = 0; nt < 4; nt++) {
            int cc = col0 + wn + nt * 8 + q * 2;
            if (r0 < M) {
                C[(size_t)r0 * N + cc]     = acc[mt][nt][0];
                C[(size_t)r0 * N + cc + 1] = acc[mt][nt][1];
            }
            if (r0 + 8 < M) {
                C[(size_t)(r0 + 8) * N + cc]     = acc[mt][nt][2];
                C[(size_t)(r0 + 8) * N + cc + 1] = acc[mt][nt][3];
            }
        }
    }

    // fused GAT scores: each warp's 32-col span lies inside one head
    if (asrc) {
        int Cm1 = (1 << shiftC) - 1;
        int hd = (col0 + wn) >> shiftC;
        float av_s[4][2], av_d[4][2];
#pragma unroll
        for (int nt = 0; nt < 4; nt++)
#pragma unroll
            for (int k = 0; k < 2; k++) {
                int ci = (col0 + wn + nt * 8 + q * 2 + k) & Cm1;
                av_s[nt][k] = asrc[(hd << shiftC) + ci];
                av_d[nt][k] = adst[(hd << shiftC) + ci];
            }
#pragma unroll
        for (int mt = 0; mt < 2; mt++) {
            float s0 = 0.f, s1 = 0.f, d0 = 0.f, d1 = 0.f;
#pragma unroll
            for (int nt = 0; nt < 4; nt++) {
                s0 += acc[mt][nt][0] * av_s[nt][0] + acc[mt][nt][1] * av_s[nt][1];
                s1 += acc[mt][nt][2] * av_s[nt][0] + acc[mt][nt][3] * av_s[nt][1];
                d0 += acc[mt][nt][0] * av_d[nt][0] + acc[mt][nt][1] * av_d[nt][1];
                d1 += acc[mt][nt][2] * av_d[nt][0] + acc[mt][nt][3] * av_d[nt][1];
            }
#pragma unroll
            for (int o = 1; o < 4; o <<= 1) {
                s0 += __shfl_xor_sync(0xffffffffu, s0, o);
                s1 += __shfl_xor_sync(0xffffffffu, s1, o);
                d0 += __shfl_xor_sync(0xffffffffu, d0, o);
                d1 += __shfl_xor_sync(0xffffffffu, d1, o);
            }
            if (q == 0) {
                int r0 = row0 + wm + mt * 16 + t4;
                if (r0 < M) {
                    atomicAdd(&ssrc[r0 * H + hd], s0);
                    atomicAdd(&sdst[r0 * H + hd], d0);
                }
                if (r0 + 8 < M) {
                    atomicAdd(&ssrc[(r0 + 8) * H + hd], s1);
                    atomicAdd(&sdst[(r0 + 8) * H + hd], d1);
                }
            }
        }
    }
}

// ---------------- CSR construction -------------------------------------------
__global__ void zero_k(int* __restrict__ cnt, int* __restrict__ pos) {
    int i = blockIdx.x * blockDim.x + threadIdx.x;
    if (i < NN) { cnt[i] = 0; pos[i] = 0; }
}
__global__ void hist_k(const int* __restrict__ ei, int* __restrict__ cnt) {
    int e = blockIdx.x * blockDim.x + threadIdx.x;
    if (e < EE) atomicAdd(&cnt[ei[EE + e]], 1);
}
__global__ void scan_k(const int* __restrict__ cnt, int* __restrict__ off) {
    __shared__ int wsum[32];
    __shared__ int carry_s;
    int t = threadIdx.x, lane = t & 31, w = t >> 5;
    if (t == 0) carry_s = 0;
    __syncthreads();
    for (int base = 0; base < NN; base += 1024) {
        int i = base + t;
        int x = (i < NN) ? cnt[i] + 1 : 0;
#pragma unroll
        for (int o = 1; o < 32; o <<= 1) {
            int y = __shfl_up_sync(0xffffffffu, x, o);
            if (lane >= o) x += y;
        }
        if (lane == 31) wsum[w] = x;
        __syncthreads();
        if (w == 0) {
            int s = wsum[lane];
#pragma unroll
            for (int o = 1; o < 32; o <<= 1) {
                int y = __shfl_up_sync(0xffffffffu, s, o);
                if (lane >= o) s += y;
            }
            wsum[lane] = s;
        }
        __syncthreads();
        int woff = (w == 0) ? 0 : wsum[w - 1];
        int total = wsum[31];
        if (i < NN) off[i + 1] = carry_s + woff + x;
        __syncthreads();
        if (t == 0) carry_s += total;
        __syncthreads();
    }
    if (threadIdx.x == 0) off[0] = 0;
}
__global__ void scatter_k(const int* __restrict__ ei, const int* __restrict__ off,
                          int* __restrict__ pos, int* __restrict__ srcs) {
    int e = blockIdx.x * blockDim.x + threadIdx.x;
    if (e >= ET) return;
    int s, d;
    if (e < EE) { s = ei[e]; d = ei[EE + e]; }
    else        { s = e - EE; d = s; }
    int p = atomicAdd(&pos[d], 1);
    srcs[off[d] + p] = s;
}

// ---------------- zero score accumulators -------------------------------------
__global__ void zs_k(float* __restrict__ a, float* __restrict__ b, int n) {
    int i = blockIdx.x * blockDim.x + threadIdx.x;
    if (i < n) { a[i] = 0.f; b[i] = 0.f; }
}

// ---------------- load H scores as a vector -----------------------------------
template<int H>
__device__ __forceinline__ void load_sv(const float* __restrict__ p, int n, float* out) {
    if (H == 4) { float4 v = *(const float4*)(p + n * 4);
                  out[0] = v.x; out[1] = v.y; out[2] = v.z; out[3] = v.w; }
    else if (H == 2) { float2 v = *(const float2*)(p + n * 2);
                       out[0] = v.x; out[1] = v.y; }
    else out[0] = p[n];
}

// ---------------- alpha: 8 lanes per dst node (4 nodes/warp), single pass -----
// Mean degree ~9 -> a full warp per node wastes ~3/4 of lanes. 8-lane subgroups
// keep the same single-pass no-max-shift math (scores O(10), exp-safe).
template<int H>
__global__ void alpha_k(const int* __restrict__ off, const int* __restrict__ srcs,
                        const float* __restrict__ ssrc, const float* __restrict__ sdst,
                        float* __restrict__ alpha, float* __restrict__ den) {
    int gt = blockIdx.x * blockDim.x + threadIdx.x;
    int n = gt >> 3;                      // 8 lanes per node
    int sl = threadIdx.x & 7;
    if (n >= NN) return;
    int laneid = threadIdx.x & 31;
    unsigned mask = 0xFFu << (laneid & ~7);   // this subgroup's lanes

    int beg = off[n], end = off[n + 1];
    float sdn[H];
    load_sv<H>(sdst, n, sdn);

    float dn[H];
#pragma unroll
    for (int hd = 0; hd < H; hd++) dn[hd] = 0.f;
    for (int j = beg + sl; j < end; j += 8) {
        int s = srcs[j];
        float sv[H], ev[H];
        load_sv<H>(ssrc, s, sv);
#pragma unroll
        for (int hd = 0; hd < H; hd++) {
            float v = sv[hd] + sdn[hd];
            v = v > 0.f ? v : 0.2f * v;
            ev[hd] = expf(v);
            dn[hd] += ev[hd];
        }
        if (H == 4)      *(float4*)(alpha + (size_t)j * 4) = make_float4(ev[0], ev[1], ev[2], ev[3]);
        else if (H == 2) *(float2*)(alpha + (size_t)j * 2) = make_float2(ev[0], ev[1]);
        else             alpha[j] = ev[0];
    }
#pragma unroll
    for (int o = 4; o; o >>= 1)
#pragma unroll
        for (int hd = 0; hd < H; hd++)
            dn[hd] += __shfl_xor_sync(mask, dn[hd], o);
    if (sl == 0) {
        if (H == 4)      *(float4*)(den + n * 4) = make_float4(dn[0], dn[1], dn[2], dn[3]);
        else if (H == 2) *(float2*)(den + n * 2) = make_float2(dn[0], dn[1]);
        else             den[n] = dn[0];
    }
}

// ---------------- fused gather-aggregate + /den + bias + LN + ELU -------------
#define AG_CHUNK 16
template<int H, int G, int SHIFT>
__global__ __launch_bounds__(128) void gat_agg_k(
        const int* __restrict__ off, const int* __restrict__ srcs,
        const float* __restrict__ alpha, const float* __restrict__ den,
        const float* __restrict__ h,
        const float* __restrict__ bias, const float* __restrict__ lng,
        const float* __restrict__ lnb, float* __restrict__ out) {
    const int NPB = 128 / G;
    const int HC = G * 4;
    __shared__ float s_alpha[NPB][AG_CHUNK][H];
    __shared__ int   s_src[NPB][AG_CHUNK];
    __shared__ float red[256];

    int t = threadIdx.x;
    int grp = t / G, g = t % G;
    int n = blockIdx.x * NPB + grp;

    int beg = off[n], end = off[n + 1];
    int c0 = g * 4;
    const int hd0 = (G * 4 == (1 << SHIFT)) ? 0 : -1;
    int myhd = (hd0 == 0) ? 0 : (c0 >> SHIFT);
    float inv_den = 1.f / den[n * H + myhd];
    float4 acc = make_float4(0.f, 0.f, 0.f, 0.f);

    for (int it = 0;; it++) {
        int cb = beg + it * AG_CHUNK;
        bool active = cb < end;
        if (!__syncthreads_or(active)) break;
        int clen = active ? min(AG_CHUNK, end - cb) : 0;
        if (g < clen) {
            s_src[grp][g] = srcs[cb + g];
            float av[H];
            load_sv<H>(alpha, cb + g, av);
#pragma unroll
            for (int hd = 0; hd < H; hd++) s_alpha[grp][g][hd] = av[hd];
        }
        __syncthreads();
        int k = 0;
        for (; k + 8 <= clen; k += 8) {
            int   si[8];
            float ai[8];
            float4 vi[8];
#pragma unroll
            for (int u = 0; u < 8; u++) {
                si[u] = s_src[grp][k + u];
                ai[u] = s_alpha[grp][k + u][myhd];
            }
#pragma unroll
            for (int u = 0; u < 8; u++)
                vi[u] = *(const float4*)(h + (size_t)si[u] * HC + c0);
#pragma unroll
            for (int u = 0; u < 8; u++) {
                acc.x += ai[u] * vi[u].x; acc.y += ai[u] * vi[u].y;
                acc.z += ai[u] * vi[u].z; acc.w += ai[u] * vi[u].w;
            }
        }
        for (; k + 4 <= clen; k += 4) {
            int s0 = s_src[grp][k],     s1 = s_src[grp][k + 1];
            int s2 = s_src[grp][k + 2], s3 = s_src[grp][k + 3];
            float a0 = s_alpha[grp][k][myhd],     a1 = s_alpha[grp][k + 1][myhd];
            float a2 = s_alpha[grp][k + 2][myhd], a3 = s_alpha[grp][k + 3][myhd];
            float4 v0 = *(const float4*)(h + (size_t)s0 * HC + c0);
            float4 v1 = *(const float4*)(h + (size_t)s1 * HC + c0);
            float4 v2 = *(const float4*)(h + (size_t)s2 * HC + c0);
            float4 v3 = *(const float4*)(h + (size_t)s3 * HC + c0);
            acc.x += a0 * v0.x; acc.y += a0 * v0.y; acc.z += a0 * v0.z; acc.w += a0 * v0.w;
            acc.x += a1 * v1.x; acc.y += a1 * v1.y; acc.z += a1 * v1.z; acc.w += a1 * v1.w;
            acc.x += a2 * v2.x; acc.y += a2 * v2.y; acc.z += a2 * v2.z; acc.w += a2 * v2.w;
            acc.x += a3 * v3.x; acc.y += a3 * v3.y; acc.z += a3 * v3.z; acc.w += a3 * v3.w;
        }
        for (; k < clen; k++) {
            float a = s_alpha[grp][k][myhd];
            float4 hv = *(const float4*)(h + (size_t)s_src[grp][k] * HC + c0);
            acc.x += a * hv.x; acc.y += a * hv.y;
            acc.z += a * hv.z; acc.w += a * hv.w;
        }
    }

    float4 b4 = *(const float4*)(bias + c0);
    float4 val;
    val.x = acc.x * inv_den + b4.x; val.y = acc.y * inv_den + b4.y;
    val.z = acc.z * inv_den + b4.z; val.w = acc.w * inv_den + b4.w;
    float sum = val.x + val.y + val.z + val.w;
    float sq  = val.x * val.x + val.y * val.y + val.z * val.z + val.w * val.w;
    red[t] = sum; red[128 + t] = sq;
    __syncthreads();
#pragma unroll
    for (int o = G >> 1; o; o >>= 1) {
        if (g < o) { red[t] += red[t + o]; red[128 + t] += red[128 + t + o]; }
        __syncthreads();
    }
    int gb = grp * G;
    float mu = red[gb] / HC;
    float var = red[128 + gb] / HC - mu * mu;
    float rstd = rsqrtf(var + LN_EPS);
    float4 g4 = *(const float4*)(lng + c0);
    float4 o4 = *(const float4*)(lnb + c0);
    float y0 = (val.x - mu) * rstd * g4.x + o4.x;
    float y1 = (val.y - mu) * rstd * g4.y + o4.y;
    float y2 = (val.z - mu) * rstd * g4.z + o4.z;
    float y3 = (val.w - mu) * rstd * g4.w + o4.w;
    float4 r;
    r.x = y0 > 0.f ? y0 : expm1f(y0);
    r.y = y1 > 0.f ? y1 : expm1f(y1);
    r.z = y2 > 0.f ? y2 : expm1f(y2);
    r.w = y3 > 0.f ? y3 : expm1f(y3);
    *(float4*)(out + (size_t)n * HC + c0) = r;
}

// ---------------- decoder epilogue: +bias -> LN -> ELU -----------------------
__global__ void ln_elu_k(const float* __restrict__ in, const float* __restrict__ bias,
                         const float* __restrict__ lng, const float* __restrict__ lnb,
                         float* __restrict__ out, int W) {
    __shared__ float sh[256];
    int n = blockIdx.x;
    int t = threadIdx.x;
    float v[4];
    float sum = 0.f, sq = 0.f;
    int cnt = 0;
    for (int c = t; c < W; c += 128) {
        float val = in[(size_t)n * W + c] + bias[c];
        v[cnt++] = val; sum += val; sq += val * val;
    }
    sh[t] = sum; sh[128 + t] = sq;
    __syncthreads();
    for (int o = 64; o; o >>= 1) {
        if (t < o) { sh[t] += sh[t + o]; sh[128 + t] += sh[128 + t + o]; }
        __syncthreads();
    }
    float mu = sh[0] / W;
    float var = sh[128] / W - mu * mu;
    float rstd = rsqrtf(var + LN_EPS);
    cnt = 0;
    for (int c = t; c < W; c += 128) {
        float y = (v[cnt++] - mu) * rstd * lng[c] + lnb[c];
        out[(size_t)n * W + c] = y > 0.f ? y : expm1f(y);
    }
}

// ---------------- host orchestration -----------------------------------------
extern "C" void kernel_launch(void* const* d_in, const int* in_sizes, int n_in,
                              void* d_out, int out_size) {
    const float* x   = (const float*)d_in[0];
    const int*   ei  = (const int*)d_in[1];
    const float* W1  = (const float*)d_in[2];
    const float* a1s = (const float*)d_in[3];
    const float* a1d = (const float*)d_in[4];
    const float* b1  = (const float*)d_in[5];
    const float* g1  = (const float*)d_in[6];
    const float* bb1 = (const float*)d_in[7];
    const float* W2  = (const float*)d_in[8];
    const float* a2s = (const float*)d_in[9];
    const float* a2d = (const float*)d_in[10];
    const float* b2  = (const float*)d_in[11];
    const float* g2  = (const float*)d_in[12];
    const float* bb2 = (const float*)d_in[13];
    const float* W3  = (const float*)d_in[14];
    const float* a3s = (const float*)d_in[15];
    const float* a3d = (const float*)d_in[16];
    const float* b3  = (const float*)d_in[17];
    const float* g3  = (const float*)d_in[18];
    const float* bb3 = (const float*)d_in[19];
    const float* dW1   = (const float*)d_in[20];
    const float* db1   = (const float*)d_in[21];
    const float* lnd1g = (const float*)d_in[22];
    const float* lnd1b = (const float*)d_in[23];
    const float* dW2   = (const float*)d_in[24];
    const float* db2   = (const float*)d_in[25];
    const float* lnd2g = (const float*)d_in[26];
    const float* lnd2b = (const float*)d_in[27];

    float *h, *feat, *ssrc, *sdst, *den, *alpha;
    int *cnt, *off, *pos, *srcs;
    cudaGetSymbolAddress((void**)&h,     g_h);
    cudaGetSymbolAddress((void**)&feat,  g_feat);
    cudaGetSymbolAddress((void**)&ssrc,  g_ssrc);
    cudaGetSymbolAddress((void**)&sdst,  g_sdst);
    cudaGetSymbolAddress((void**)&den,   g_den);
    cudaGetSymbolAddress((void**)&alpha, g_alpha);
    cudaGetSymbolAddress((void**)&cnt,   g_cnt);
    cudaGetSymbolAddress((void**)&off,   g_off);
    cudaGetSymbolAddress((void**)&pos,   g_pos);
    cudaGetSymbolAddress((void**)&srcs,  g_srcs);

    // side stream + events (created once; never destroyed -> capture-safe)
    static cudaStream_t s2 = nullptr;
    static cudaEvent_t ev_fork = nullptr, ev_join = nullptr;
    if (!s2) {
        cudaStreamCreateWithFlags(&s2, cudaStreamNonBlocking);
        cudaEventCreateWithFlags(&ev_fork, cudaEventDisableTiming);
        cudaEventCreateWithFlags(&ev_join, cudaEventDisableTiming);
    }

    // ---- fork: CSR build on s2, overlapped with layer-1 zs+GEMM on main ----
    cudaEventRecord(ev_fork, 0);
    cudaStreamWaitEvent(s2, ev_fork, 0);
    zero_k<<<(NN + 255) / 256, 256, 0, s2>>>(cnt, pos);
    hist_k<<<(EE + 255) / 256, 256, 0, s2>>>(ei, cnt);
    scan_k<<<1, 1024, 0, s2>>>(cnt, off);
    scatter_k<<<(ET + 255) / 256, 256, 0, s2>>>(ei, off, pos, srcs);
    cudaEventRecord(ev_join, s2);

    const int MB = (NN + 127) / 128;
    auto run_gemm = [&](const float* A, const float* B, float* C, int N, int K,
                        const float* as_, const float* ad_, int H, int shiftC) {
        gemm_bf16x3<<<dim3(N / 64, MB), 256>>>(A, B, C, NN, N, K,
                                               ssrc, sdst, as_, ad_, H, shiftC);
    };

    // ---- layer 1: H=4, C=128, HC=512, G=128, NPB=1 ----
    zs_k<<<(NN * 4 + 255) / 256, 256>>>(ssrc, sdst, NN * 4);
    run_gemm(x, W1, h, 512, 128, a1s, a1d, 4, 7);
    cudaStreamWaitEvent(0, ev_join, 0);   // join: alpha needs the CSR
    alpha_k<4><<<(NN * 8 + 255) / 256, 256>>>(off, srcs, ssrc, sdst, alpha, den);
    gat_agg_k<4, 128, 7><<<NN, 128>>>(off, srcs, alpha, den, h, b1, g1, bb1, feat);

    // ---- layer 2: H=2, C=128, HC=256, G=64, NPB=2 ----
    zs_k<<<(NN * 2 + 255) / 256, 256>>>(ssrc, sdst, NN * 2);
    run_gemm(feat, W2, h, 256, 512, a2s, a2d, 2, 7);
    alpha_k<2><<<(NN * 8 + 255) / 256, 256>>>(off, srcs, ssrc, sdst, alpha, den);
    gat_agg_k<2, 64, 7><<<NN / 2, 128>>>(off, srcs, alpha, den, h, b2, g2, bb2, feat);

    // ---- layer 3: H=1, C=64, HC=64, G=16, NPB=8 ----
    zs_k<<<(NN + 255) / 256, 256>>>(ssrc, sdst, NN);
    run_gemm(feat, W3, h, 64, 256, a3s, a3d, 1, 6);
    alpha_k<1><<<(NN * 8 + 255) / 256, 256>>>(off, srcs, ssrc, sdst, alpha, den);
    gat_agg_k<1, 16, 6><<<NN / 8, 128>>>(off, srcs, alpha, den, h, b3, g3, bb3, feat);

    // ---- decoder ----
    run_gemm(feat, dW1, h, 128, 64, nullptr, nullptr, 1, 0);
    ln_elu_k<<<NN, 128>>>(h, db1, lnd1g, lnd1b, feat, 128);
    run_gemm(feat, dW2, h, 128, 128, nullptr, nullptr, 1, 0);
    ln_elu_k<<<NN, 128>>>(h, db2, lnd2g, lnd2b, (float*)d_out, 128);
}

// round 17
// speedup vs baseline: 1.1925x; 1.1353x over previous
#include <cuda_runtime.h>
#include <cuda_bf16.h>
#include <math.h>
#include <stdint.h>

#define NN 50000
#define EE 400000
#define ET 450000      // EE + NN self loops
#define LN_EPS 1e-5f

// ---------------- scratch (device globals; allocation is forbidden) ----------
__device__ float g_h[(size_t)NN * 512];
__device__ float g_feat[(size_t)NN * 512];
__device__ float g_ssrc[NN * 4];
__device__ float g_sdst[NN * 4];
__device__ float g_den[NN * 4];
__device__ float g_alpha[(size_t)ET * 4];
__device__ int   g_cnt[NN];
__device__ int   g_off[NN + 1];
__device__ int   g_pos[NN];
__device__ int   g_srcs[ET];

// ---------------- bf16x3 helpers ----------------------------------------------
__device__ __forceinline__ uint32_t pack_hi(float x, float y, float& lx, float& ly) {
    __nv_bfloat16 hx = __float2bfloat16_rn(x);
    __nv_bfloat16 hy = __float2bfloat16_rn(y);
    lx = x - __bfloat162float(hx);
    ly = y - __bfloat162float(hy);
    __nv_bfloat162 p = __halves2bfloat162(hx, hy);
    return *(uint32_t*)&p;
}
__device__ __forceinline__ uint32_t pack_lo(float lx, float ly) {
    __nv_bfloat162 p = __halves2bfloat162(__float2bfloat16_rn(lx),
                                          __float2bfloat16_rn(ly));
    return *(uint32_t*)&p;
}
__device__ __forceinline__ void mma_bf16(float* c, const uint32_t* a, const uint32_t* b) {
    asm volatile(
        "mma.sync.aligned.m16n8k16.row.col.f32.bf16.bf16.f32 "
        "{%0,%1,%2,%3}, {%4,%5,%6,%7}, {%8,%9}, {%0,%1,%2,%3};"
        : "+f"(c[0]), "+f"(c[1]), "+f"(c[2]), "+f"(c[3])
        : "r"(a[0]), "r"(a[1]), "r"(a[2]), "r"(a[3]), "r"(b[0]), "r"(b[1]));
}

// ---------------- bf16x3 GEMM, 128x64 tile + fused GAT scores -----------------
__global__ __launch_bounds__(256) void gemm_bf16x3(
        const float* __restrict__ A, const float* __restrict__ B,
        float* __restrict__ C, int M, int N, int K,
        float* ssrc, float* sdst, const float* __restrict__ asrc,
        const float* __restrict__ adst, int H, int shiftC) {
    __shared__ uint32_t Ahi[2][8][136], Alo[2][8][136];
    __shared__ uint32_t Bhi[2][8][72],  Blo[2][8][72];

    int tid = threadIdx.x;
    int lane = tid & 31, wid = tid >> 5;
    int wm = (wid >> 1) * 32;
    int wn = (wid & 1) * 32;
    int q = lane & 3, t4 = lane >> 2;
    int row0 = blockIdx.y * 128, col0 = blockIdx.x * 64;

    int a_r = tid >> 2, a_k2 = (tid & 3) * 2;
    int b_k2 = tid >> 5, b_n = lane * 2;

    float4 pa[2];
    float2 pb0, pb1;

    auto prefetch = [&](int k0) {
#pragma unroll
        for (int i = 0; i < 2; i++) {
            int r = row0 + a_r + i * 64;
            if (r < M) pa[i] = *(const float4*)(A + (size_t)r * K + k0 + a_k2 * 2);
            else       pa[i] = make_float4(0.f, 0.f, 0.f, 0.f);
        }
        const float* bp = B + (size_t)(k0 + b_k2 * 2) * N + col0 + b_n;
        pb0 = *(const float2*)bp;
        pb1 = *(const float2*)(bp + N);
    };

    auto convert_store = [&](int buf) {
#pragma unroll
        for (int i = 0; i < 2; i++) {
            int r = a_r + i * 64;
            float lx, ly, lz, lw;
            uint32_t h0 = pack_hi(pa[i].x, pa[i].y, lx, ly);
            uint32_t h1 = pack_hi(pa[i].z, pa[i].w, lz, lw);
            Ahi[buf][a_k2][r]     = h0;
            Ahi[buf][a_k2 + 1][r] = h1;
            Alo[buf][a_k2][r]     = pack_lo(lx, ly);
            Alo[buf][a_k2 + 1][r] = pack_lo(lz, lw);
        }
        {
            float l00, l10, l01, l11;
            uint32_t h0 = pack_hi(pb0.x, pb1.x, l00, l10);
            uint32_t h1 = pack_hi(pb0.y, pb1.y, l01, l11);
            Bhi[buf][b_k2][b_n]     = h0;
            Bhi[buf][b_k2][b_n + 1] = h1;
            Blo[buf][b_k2][b_n]     = pack_lo(l00, l10);
            Blo[buf][b_k2][b_n + 1] = pack_lo(l01, l11);
        }
    };

    float acc[2][4][4];
#pragma unroll
    for (int i = 0; i < 2; i++)
#pragma unroll
        for (int j = 0; j < 4; j++)
#pragma unroll
            for (int k = 0; k < 4; k++) acc[i][j][k] = 0.f;

    int ntiles = K >> 4;
    prefetch(0);
    convert_store(0);
    __syncthreads();

    int buf = 0;
    for (int t = 0; t < ntiles; t++) {
        if (t + 1 < ntiles) prefetch((t + 1) << 4);

        uint32_t ah[2][4], al[2][4], bh[4][2], bl[4][2];
#pragma unroll
        for (int mt = 0; mt < 2; mt++) {
            int m0 = wm + mt * 16 + t4;
            ah[mt][0] = Ahi[buf][q][m0];     ah[mt][1] = Ahi[buf][q][m0 + 8];
            ah[mt][2] = Ahi[buf][q + 4][m0]; ah[mt][3] = Ahi[buf][q + 4][m0 + 8];
            al[mt][0] = Alo[buf][q][m0];     al[mt][1] = Alo[buf][q][m0 + 8];
            al[mt][2] = Alo[buf][q + 4][m0]; al[mt][3] = Alo[buf][q + 4][m0 + 8];
        }
#pragma unroll
        for (int nt = 0; nt < 4; nt++) {
            int n0 = wn + nt * 8 + t4;
            bh[nt][0] = Bhi[buf][q][n0]; bh[nt][1] = Bhi[buf][q + 4][n0];
            bl[nt][0] = Blo[buf][q][n0]; bl[nt][1] = Blo[buf][q + 4][n0];
        }
#pragma unroll
        for (int mt = 0; mt < 2; mt++)
#pragma unroll
            for (int nt = 0; nt < 4; nt++) {
                mma_bf16(acc[mt][nt], ah[mt], bh[nt]);
                mma_bf16(acc[mt][nt], ah[mt], bl[nt]);
                mma_bf16(acc[mt][nt], al[mt], bh[nt]);
            }

        if (t + 1 < ntiles) convert_store(buf ^ 1);
        __syncthreads();
        buf ^= 1;
    }

#pragma unroll
    for (int mt = 0; mt < 2; mt++) {
        int r0 = row0 + wm + mt * 16 + t4;
#pragma unroll
        for (int nt = 0; nt < 4; nt++) {
            int cc = col0 + wn + nt * 8 + q * 2;
            if (r0 < M) {
                C[(size_t)r0 * N + cc]     = acc[mt][nt][0];
                C[(size_t)r0 * N + cc + 1] = acc[mt][nt][1];
            }
            if (r0 + 8 < M) {
                C[(size_t)(r0 + 8) * N + cc]     = acc[mt][nt][2];
                C[(size_t)(r0 + 8) * N + cc + 1] = acc[mt][nt][3];
            }
        }
    }

    // fused GAT scores: each warp's 32-col span lies inside one head
    if (asrc) {
        int Cm1 = (1 << shiftC) - 1;
        int hd = (col0 + wn) >> shiftC;
        float av_s[4][2], av_d[4][2];
#pragma unroll
        for (int nt = 0; nt < 4; nt++)
#pragma unroll
            for (int k = 0; k < 2; k++) {
                int ci = (col0 + wn + nt * 8 + q * 2 + k) & Cm1;
                av_s[nt][k] = asrc[(hd << shiftC) + ci];
                av_d[nt][k] = adst[(hd << shiftC) + ci];
            }
#pragma unroll
        for (int mt = 0; mt < 2; mt++) {
            float s0 = 0.f, s1 = 0.f, d0 = 0.f, d1 = 0.f;
#pragma unroll
            for (int nt = 0; nt < 4; nt++) {
                s0 += acc[mt][nt][0] * av_s[nt][0] + acc[mt][nt][1] * av_s[nt][1];
                s1 += acc[mt][nt][2] * av_s[nt][0] + acc[mt][nt][3] * av_s[nt][1];
                d0 += acc[mt][nt][0] * av_d[nt][0] + acc[mt][nt][1] * av_d[nt][1];
                d1 += acc[mt][nt][2] * av_d[nt][0] + acc[mt][nt][3] * av_d[nt][1];
            }
#pragma unroll
            for (int o = 1; o < 4; o <<= 1) {
                s0 += __shfl_xor_sync(0xffffffffu, s0, o);
                s1 += __shfl_xor_sync(0xffffffffu, s1, o);
                d0 += __shfl_xor_sync(0xffffffffu, d0, o);
                d1 += __shfl_xor_sync(0xffffffffu, d1, o);
            }
            if (q == 0) {
                int r0 = row0 + wm + mt * 16 + t4;
                if (r0 < M) {
                    atomicAdd(&ssrc[r0 * H + hd], s0);
                    atomicAdd(&sdst[r0 * H + hd], d0);
                }
                if (r0 + 8 < M) {
                    atomicAdd(&ssrc[(r0 + 8) * H + hd], s1);
                    atomicAdd(&sdst[(r0 + 8) * H + hd], d1);
                }
            }
        }
    }
}

// ---------------- fused decoder: GEMM(128 cols) + bias + LN + ELU -------------
// 128x128 block tile (R7-verified fragment layout), row LN fully in-block.
__global__ __launch_bounds__(256) void fused_dec_k(
        const float* __restrict__ A, int K, const float* __restrict__ B,
        const float* __restrict__ bias, const float* __restrict__ lng,
        const float* __restrict__ lnb, float* __restrict__ out, int M) {
    __shared__ uint32_t Ahi[2][8][136], Alo[2][8][136];
    __shared__ uint32_t Bhi[2][8][136], Blo[2][8][136];
    __shared__ float rs[128][4], rq[128][4];
    const int N = 128;

    int tid = threadIdx.x;
    int lane = tid & 31, wid = tid >> 5;
    int wm = (wid >> 2) * 64;
    int wn = (wid & 3) * 32;
    int q = lane & 3, t4 = lane >> 2;
    int row0 = blockIdx.x * 128;

    int a_r = tid >> 2, a_k2 = (tid & 3) * 2;
    int b_k2 = (tid >> 6) * 2, b_n = (tid & 63) * 2;

    float4 pa[2];
    float2 pb[4];

    auto prefetch = [&](int k0) {
#pragma unroll
        for (int i = 0; i < 2; i++) {
            int r = row0 + a_r + i * 64;
            if (r < M) pa[i] = *(const float4*)(A + (size_t)r * K + k0 + a_k2 * 2);
            else       pa[i] = make_float4(0.f, 0.f, 0.f, 0.f);
        }
        const float* bp = B + (size_t)(k0 + b_k2 * 2) * N + b_n;
#pragma unroll
        for (int i = 0; i < 4; i++) pb[i] = *(const float2*)(bp + (size_t)i * N);
    };

    auto convert_store = [&]() {
#pragma unroll
        for (int i = 0; i < 2; i++) {
            int r = a_r + i * 64;
            float lx, ly, lz, lw;
            uint32_t h0 = pack_hi(pa[i].x, pa[i].y, lx, ly);
            uint32_t h1 = pack_hi(pa[i].z, pa[i].w, lz, lw);
            Ahi[0][a_k2][r]     = h0;
            Ahi[0][a_k2 + 1][r] = h1;
            Alo[0][a_k2][r]     = pack_lo(lx, ly);
            Alo[0][a_k2 + 1][r] = pack_lo(lz, lw);
        }
#pragma unroll
        for (int i = 0; i < 2; i++) {
            float l0, l1, l2, l3;
            uint32_t h0 = pack_hi(pb[2 * i].x, pb[2 * i + 1].x, l0, l1);
            uint32_t h1 = pack_hi(pb[2 * i].y, pb[2 * i + 1].y, l2, l3);
            Bhi[0][b_k2 + i][b_n]     = h0;
            Bhi[0][b_k2 + i][b_n + 1] = h1;
            Blo[0][b_k2 + i][b_n]     = pack_lo(l0, l1);
            Blo[0][b_k2 + i][b_n + 1] = pack_lo(l2, l3);
        }
    };
    // NOTE: single-buffered (small ntiles); sync around convert/use below.

    float acc[4][4][4];
#pragma unroll
    for (int i = 0; i < 4; i++)
#pragma unroll
        for (int j = 0; j < 4; j++)
#pragma unroll
            for (int k = 0; k < 4; k++) acc[i][j][k] = 0.f;

    int ntiles = K >> 4;
    prefetch(0);
    for (int t = 0; t < ntiles; t++) {
        convert_store();
        __syncthreads();
        if (t + 1 < ntiles) prefetch((t + 1) << 4);

        uint32_t ah[4][4], al[4][4], bh[4][2], bl[4][2];
#pragma unroll
        for (int mt = 0; mt < 4; mt++) {
            int m0 = wm + mt * 16 + t4;
            ah[mt][0] = Ahi[0][q][m0];     ah[mt][1] = Ahi[0][q][m0 + 8];
            ah[mt][2] = Ahi[0][q + 4][m0]; ah[mt][3] = Ahi[0][q + 4][m0 + 8];
            al[mt][0] = Alo[0][q][m0];     al[mt][1] = Alo[0][q][m0 + 8];
            al[mt][2] = Alo[0][q + 4][m0]; al[mt][3] = Alo[0][q + 4][m0 + 8];
        }
#pragma unroll
        for (int nt = 0; nt < 4; nt++) {
            int n0 = wn + nt * 8 + t4;
            bh[nt][0] = Bhi[0][q][n0]; bh[nt][1] = Bhi[0][q + 4][n0];
            bl[nt][0] = Blo[0][q][n0]; bl[nt][1] = Blo[0][q + 4][n0];
        }
#pragma unroll
        for (int mt = 0; mt < 4; mt++)
#pragma unroll
            for (int nt = 0; nt < 4; nt++) {
                mma_bf16(acc[mt][nt], ah[mt], bh[nt]);
                mma_bf16(acc[mt][nt], ah[mt], bl[nt]);
                mma_bf16(acc[mt][nt], al[mt], bh[nt]);
            }
        __syncthreads();
    }

    // ---- epilogue: +bias, row LN (128 cols in-block), ELU, store ----
    float bv[4][2], gv[4][2], ov[4][2];
#pragma unroll
    for (int nt = 0; nt < 4; nt++) {
        int cc = wn + nt * 8 + q * 2;
        bv[nt][0] = bias[cc]; bv[nt][1] = bias[cc + 1];
        gv[nt][0] = lng[cc];  gv[nt][1] = lng[cc + 1];
        ov[nt][0] = lnb[cc];  ov[nt][1] = lnb[cc + 1];
    }
#pragma unroll
    for (int mt = 0; mt < 4; mt++)
#pragma unroll
        for (int nt = 0; nt < 4; nt++) {
            acc[mt][nt][0] += bv[nt][0]; acc[mt][nt][1] += bv[nt][1];
            acc[mt][nt][2] += bv[nt][0]; acc[mt][nt][3] += bv[nt][1];
        }
#pragma unroll
    for (int mt = 0; mt < 4; mt++)
#pragma unroll
        for (int half = 0; half < 2; half++) {
            float s = 0.f, ss = 0.f;
#pragma unroll
            for (int nt = 0; nt < 4; nt++) {
                float a = acc[mt][nt][2 * half], b = acc[mt][nt][2 * half + 1];
                s += a + b; ss += a * a + b * b;
            }
            s  += __shfl_xor_sync(0xffffffffu, s, 1);
            s  += __shfl_xor_sync(0xffffffffu, s, 2);
            ss += __shfl_xor_sync(0xffffffffu, ss, 1);
            ss += __shfl_xor_sync(0xffffffffu, ss, 2);
            if (q == 0) {
                int r = wm + mt * 16 + t4 + half * 8;
                rs[r][wid & 3] = s;
                rq[r][wid & 3] = ss;
            }
        }
    __syncthreads();
#pragma unroll
    for (int mt = 0; mt < 4; mt++)
#pragma unroll
        for (int half = 0; half < 2; half++) {
            int r = wm + mt * 16 + t4 + half * 8;
            int gr = row0 + r;
            if (gr >= M) continue;
            float mu  = (rs[r][0] + rs[r][1] + rs[r][2] + rs[r][3]) * (1.f / 128.f);
            float var = (rq[r][0] + rq[r][1] + rq[r][2] + rq[r][3]) * (1.f / 128.f) - mu * mu;
            float rstd = rsqrtf(var + LN_EPS);
#pragma unroll
            for (int nt = 0; nt < 4; nt++) {
                int cc = wn + nt * 8 + q * 2;
                float y0 = (acc[mt][nt][2 * half]     - mu) * rstd * gv[nt][0] + ov[nt][0];
                float y1 = (acc[mt][nt][2 * half + 1] - mu) * rstd * gv[nt][1] + ov[nt][1];
                out[(size_t)gr * N + cc]     = y0 > 0.f ? y0 : expm1f(y0);
                out[(size_t)gr * N + cc + 1] = y1 > 0.f ? y1 : expm1f(y1);
            }
        }
}

// ---------------- CSR construction -------------------------------------------
__global__ void zero_k(int* __restrict__ cnt, int* __restrict__ pos) {
    int i = blockIdx.x * blockDim.x + threadIdx.x;
    if (i < NN) { cnt[i] = 0; pos[i] = 0; }
}
__global__ void hist_k(const int* __restrict__ ei, int* __restrict__ cnt) {
    int e = blockIdx.x * blockDim.x + threadIdx.x;
    if (e < EE) atomicAdd(&cnt[ei[EE + e]], 1);
}
__global__ void scan_k(const int* __restrict__ cnt, int* __restrict__ off) {
    __shared__ int wsum[32];
    __shared__ int carry_s;
    int t = threadIdx.x, lane = t & 31, w = t >> 5;
    if (t == 0) carry_s = 0;
    __syncthreads();
    for (int base = 0; base < NN; base += 1024) {
        int i = base + t;
        int x = (i < NN) ? cnt[i] + 1 : 0;
#pragma unroll
        for (int o = 1; o < 32; o <<= 1) {
            int y = __shfl_up_sync(0xffffffffu, x, o);
            if (lane >= o) x += y;
        }
        if (lane == 31) wsum[w] = x;
        __syncthreads();
        if (w == 0) {
            int s = wsum[lane];
#pragma unroll
            for (int o = 1; o < 32; o <<= 1) {
                int y = __shfl_up_sync(0xffffffffu, s, o);
                if (lane >= o) s += y;
            }
            wsum[lane] = s;
        }
        __syncthreads();
        int woff = (w == 0) ? 0 : wsum[w - 1];
        int total = wsum[31];
        if (i < NN) off[i + 1] = carry_s + woff + x;
        __syncthreads();
        if (t == 0) carry_s += total;
        __syncthreads();
    }
    if (threadIdx.x == 0) off[0] = 0;
}
__global__ void scatter_k(const int* __restrict__ ei, const int* __restrict__ off,
                          int* __restrict__ pos, int* __restrict__ srcs) {
    int e = blockIdx.x * blockDim.x + threadIdx.x;
    if (e >= ET) return;
    int s, d;
    if (e < EE) { s = ei[e]; d = ei[EE + e]; }
    else        { s = e - EE; d = s; }
    int p = atomicAdd(&pos[d], 1);
    srcs[off[d] + p] = s;
}

// ---------------- zero score accumulators (layer 1 only) ----------------------
__global__ void zs_k(float* __restrict__ a, float* __restrict__ b, int n) {
    int i = blockIdx.x * blockDim.x + threadIdx.x;
    if (i < n) { a[i] = 0.f; b[i] = 0.f; }
}

// ---------------- load H scores as a vector -----------------------------------
template<int H>
__device__ __forceinline__ void load_sv(const float* __restrict__ p, int n, float* out) {
    if (H == 4) { float4 v = *(const float4*)(p + n * 4);
                  out[0] = v.x; out[1] = v.y; out[2] = v.z; out[3] = v.w; }
    else if (H == 2) { float2 v = *(const float2*)(p + n * 2);
                       out[0] = v.x; out[1] = v.y; }
    else out[0] = p[n];
}

// ---------------- alpha: 8 lanes per dst node (4 nodes/warp), single pass -----
template<int H>
__global__ void alpha_k(const int* __restrict__ off, const int* __restrict__ srcs,
                        const float* __restrict__ ssrc, const float* __restrict__ sdst,
                        float* __restrict__ alpha, float* __restrict__ den) {
    int gt = blockIdx.x * blockDim.x + threadIdx.x;
    int n = gt >> 3;
    int sl = threadIdx.x & 7;
    if (n >= NN) return;
    int laneid = threadIdx.x & 31;
    unsigned mask = 0xFFu << (laneid & ~7);

    int beg = off[n], end = off[n + 1];
    float sdn[H];
    load_sv<H>(sdst, n, sdn);

    float dn[H];
#pragma unroll
    for (int hd = 0; hd < H; hd++) dn[hd] = 0.f;
    for (int j = beg + sl; j < end; j += 8) {
        int s = srcs[j];
        float sv[H], ev[H];
        load_sv<H>(ssrc, s, sv);
#pragma unroll
        for (int hd = 0; hd < H; hd++) {
            float v = sv[hd] + sdn[hd];
            v = v > 0.f ? v : 0.2f * v;
            ev[hd] = expf(v);
            dn[hd] += ev[hd];
        }
        if (H == 4)      *(float4*)(alpha + (size_t)j * 4) = make_float4(ev[0], ev[1], ev[2], ev[3]);
        else if (H == 2) *(float2*)(alpha + (size_t)j * 2) = make_float2(ev[0], ev[1]);
        else             alpha[j] = ev[0];
    }
#pragma unroll
    for (int o = 4; o; o >>= 1)
#pragma unroll
        for (int hd = 0; hd < H; hd++)
            dn[hd] += __shfl_xor_sync(mask, dn[hd], o);
    if (sl == 0) {
        if (H == 4)      *(float4*)(den + n * 4) = make_float4(dn[0], dn[1], dn[2], dn[3]);
        else if (H == 2) *(float2*)(den + n * 2) = make_float2(dn[0], dn[1]);
        else             den[n] = dn[0];
    }
}

// ---------------- fused gather-aggregate + /den + bias + LN + ELU -------------
// HNEXT > 0: also zero next layer's score accumulators for node n.
#define AG_CHUNK 16
template<int H, int G, int SHIFT, int HNEXT>
__global__ __launch_bounds__(128) void gat_agg_k(
        const int* __restrict__ off, const int* __restrict__ srcs,
        const float* __restrict__ alpha, const float* __restrict__ den,
        const float* __restrict__ h,
        const float* __restrict__ bias, const float* __restrict__ lng,
        const float* __restrict__ lnb, float* __restrict__ out,
        float* zs_a, float* zs_b) {
    const int NPB = 128 / G;
    const int HC = G * 4;
    __shared__ float s_alpha[NPB][AG_CHUNK][H];
    __shared__ int   s_src[NPB][AG_CHUNK];
    __shared__ float red[256];

    int t = threadIdx.x;
    int grp = t / G, g = t % G;
    int n = blockIdx.x * NPB + grp;

    if (HNEXT > 0 && g < HNEXT) {
        zs_a[n * HNEXT + g] = 0.f;
        zs_b[n * HNEXT + g] = 0.f;
    }

    int beg = off[n], end = off[n + 1];
    int c0 = g * 4;
    const int hd0 = (G * 4 == (1 << SHIFT)) ? 0 : -1;
    int myhd = (hd0 == 0) ? 0 : (c0 >> SHIFT);
    float inv_den = 1.f / den[n * H + myhd];
    float4 acc = make_float4(0.f, 0.f, 0.f, 0.f);

    for (int it = 0;; it++) {
        int cb = beg + it * AG_CHUNK;
        bool active = cb < end;
        if (!__syncthreads_or(active)) break;
        int clen = active ? min(AG_CHUNK, end - cb) : 0;
        if (g < clen) {
            s_src[grp][g] = srcs[cb + g];
            float av[H];
            load_sv<H>(alpha, cb + g, av);
#pragma unroll
            for (int hd = 0; hd < H; hd++) s_alpha[grp][g][hd] = av[hd];
        }
        __syncthreads();
        int k = 0;
        for (; k + 8 <= clen; k += 8) {
            int   si[8];
            float ai[8];
            float4 vi[8];
#pragma unroll
            for (int u = 0; u < 8; u++) {
                si[u] = s_src[grp][k + u];
                ai[u] = s_alpha[grp][k + u][myhd];
            }
#pragma unroll
            for (int u = 0; u < 8; u++)
                vi[u] = *(const float4*)(h + (size_t)si[u] * HC + c0);
#pragma unroll
            for (int u = 0; u < 8; u++) {
                acc.x += ai[u] * vi[u].x; acc.y += ai[u] * vi[u].y;
                acc.z += ai[u] * vi[u].z; acc.w += ai[u] * vi[u].w;
            }
        }
        for (; k + 4 <= clen; k += 4) {
            int s0 = s_src[grp][k],     s1 = s_src[grp][k + 1];
            int s2 = s_src[grp][k + 2], s3 = s_src[grp][k + 3];
            float a0 = s_alpha[grp][k][myhd],     a1 = s_alpha[grp][k + 1][myhd];
            float a2 = s_alpha[grp][k + 2][myhd], a3 = s_alpha[grp][k + 3][myhd];
            float4 v0 = *(const float4*)(h + (size_t)s0 * HC + c0);
            float4 v1 = *(const float4*)(h + (size_t)s1 * HC + c0);
            float4 v2 = *(const float4*)(h + (size_t)s2 * HC + c0);
            float4 v3 = *(const float4*)(h + (size_t)s3 * HC + c0);
            acc.x += a0 * v0.x; acc.y += a0 * v0.y; acc.z += a0 * v0.z; acc.w += a0 * v0.w;
            acc.x += a1 * v1.x; acc.y += a1 * v1.y; acc.z += a1 * v1.z; acc.w += a1 * v1.w;
            acc.x += a2 * v2.x; acc.y += a2 * v2.y; acc.z += a2 * v2.z; acc.w += a2 * v2.w;
            acc.x += a3 * v3.x; acc.y += a3 * v3.y; acc.z += a3 * v3.z; acc.w += a3 * v3.w;
        }
        for (; k < clen; k++) {
            float a = s_alpha[grp][k][myhd];
            float4 hv = *(const float4*)(h + (size_t)s_src[grp][k] * HC + c0);
            acc.x += a * hv.x; acc.y += a * hv.y;
            acc.z += a * hv.z; acc.w += a * hv.w;
        }
    }

    float4 b4 = *(const float4*)(bias + c0);
    float4 val;
    val.x = acc.x * inv_den + b4.x; val.y = acc.y * inv_den + b4.y;
    val.z = acc.z * inv_den + b4.z; val.w = acc.w * inv_den + b4.w;
    float sum = val.x + val.y + val.z + val.w;
    float sq  = val.x * val.x + val.y * val.y + val.z * val.z + val.w * val.w;
    red[t] = sum; red[128 + t] = sq;
    __syncthreads();
#pragma unroll
    for (int o = G >> 1; o; o >>= 1) {
        if (g < o) { red[t] += red[t + o]; red[128 + t] += red[128 + t + o]; }
        __syncthreads();
    }
    int gb = grp * G;
    float mu = red[gb] / HC;
    float var = red[128 + gb] / HC - mu * mu;
    float rstd = rsqrtf(var + LN_EPS);
    float4 g4 = *(const float4*)(lng + c0);
    float4 o4 = *(const float4*)(lnb + c0);
    float y0 = (val.x - mu) * rstd * g4.x + o4.x;
    float y1 = (val.y - mu) * rstd * g4.y + o4.y;
    float y2 = (val.z - mu) * rstd * g4.z + o4.z;
    float y3 = (val.w - mu) * rstd * g4.w + o4.w;
    float4 r;
    r.x = y0 > 0.f ? y0 : expm1f(y0);
    r.y = y1 > 0.f ? y1 : expm1f(y1);
    r.z = y2 > 0.f ? y2 : expm1f(y2);
    r.w = y3 > 0.f ? y3 : expm1f(y3);
    *(float4*)(out + (size_t)n * HC + c0) = r;
}

// ---------------- host orchestration -----------------------------------------
extern "C" void kernel_launch(void* const* d_in, const int* in_sizes, int n_in,
                              void* d_out, int out_size) {
    const float* x   = (const float*)d_in[0];
    const int*   ei  = (const int*)d_in[1];
    const float* W1  = (const float*)d_in[2];
    const float* a1s = (const float*)d_in[3];
    const float* a1d = (const float*)d_in[4];
    const float* b1  = (const float*)d_in[5];
    const float* g1  = (const float*)d_in[6];
    const float* bb1 = (const float*)d_in[7];
    const float* W2  = (const float*)d_in[8];
    const float* a2s = (const float*)d_in[9];
    const float* a2d = (const float*)d_in[10];
    const float* b2  = (const float*)d_in[11];
    const float* g2  = (const float*)d_in[12];
    const float* bb2 = (const float*)d_in[13];
    const float* W3  = (const float*)d_in[14];
    const float* a3s = (const float*)d_in[15];
    const float* a3d = (const float*)d_in[16];
    const float* b3  = (const float*)d_in[17];
    const float* g3  = (const float*)d_in[18];
    const float* bb3 = (const float*)d_in[19];
    const float* dW1   = (const float*)d_in[20];
    const float* db1   = (const float*)d_in[21];
    const float* lnd1g = (const float*)d_in[22];
    const float* lnd1b = (const float*)d_in[23];
    const float* dW2   = (const float*)d_in[24];
    const float* db2   = (const float*)d_in[25];
    const float* lnd2g = (const float*)d_in[26];
    const float* lnd2b = (const float*)d_in[27];

    float *h, *feat, *ssrc, *sdst, *den, *alpha;
    int *cnt, *off, *pos, *srcs;
    cudaGetSymbolAddress((void**)&h,     g_h);
    cudaGetSymbolAddress((void**)&feat,  g_feat);
    cudaGetSymbolAddress((void**)&ssrc,  g_ssrc);
    cudaGetSymbolAddress((void**)&sdst,  g_sdst);
    cudaGetSymbolAddress((void**)&den,   g_den);
    cudaGetSymbolAddress((void**)&alpha, g_alpha);
    cudaGetSymbolAddress((void**)&cnt,   g_cnt);
    cudaGetSymbolAddress((void**)&off,   g_off);
    cudaGetSymbolAddress((void**)&pos,   g_pos);
    cudaGetSymbolAddress((void**)&srcs,  g_srcs);

    // side stream + events (created once; never destroyed -> capture-safe)
    static cudaStream_t s2 = nullptr;
    static cudaEvent_t ev_fork = nullptr, ev_join = nullptr;
    if (!s2) {
        cudaStreamCreateWithFlags(&s2, cudaStreamNonBlocking);
        cudaEventCreateWithFlags(&ev_fork, cudaEventDisableTiming);
        cudaEventCreateWithFlags(&ev_join, cudaEventDisableTiming);
    }

    // ---- fork: CSR build on s2, overlapped with layer-1 zs+GEMM on main ----
    cudaEventRecord(ev_fork, 0);
    cudaStreamWaitEvent(s2, ev_fork, 0);
    zero_k<<<(NN + 255) / 256, 256, 0, s2>>>(cnt, pos);
    hist_k<<<(EE + 255) / 256, 256, 0, s2>>>(ei, cnt);
    scan_k<<<1, 1024, 0, s2>>>(cnt, off);
    scatter_k<<<(ET + 255) / 256, 256, 0, s2>>>(ei, off, pos, srcs);
    cudaEventRecord(ev_join, s2);

    const int MB = (NN + 127) / 128;
    auto run_gemm = [&](const float* A, const float* B, float* C, int N, int K,
                        const float* as_, const float* ad_, int H, int shiftC) {
        gemm_bf16x3<<<dim3(N / 64, MB), 256>>>(A, B, C, NN, N, K,
                                               ssrc, sdst, as_, ad_, H, shiftC);
    };

    // ---- layer 1: H=4, C=128, HC=512, G=128, NPB=1 ----
    zs_k<<<(NN * 4 + 255) / 256, 256>>>(ssrc, sdst, NN * 4);
    run_gemm(x, W1, h, 512, 128, a1s, a1d, 4, 7);
    cudaStreamWaitEvent(0, ev_join, 0);
    alpha_k<4><<<(NN * 8 + 255) / 256, 256>>>(off, srcs, ssrc, sdst, alpha, den);
    gat_agg_k<4, 128, 7, 2><<<NN, 128>>>(off, srcs, alpha, den, h, b1, g1, bb1,
                                         feat, ssrc, sdst);

    // ---- layer 2: H=2, C=128, HC=256, G=64, NPB=2 ----
    run_gemm(feat, W2, h, 256, 512, a2s, a2d, 2, 7);
    alpha_k<2><<<(NN * 8 + 255) / 256, 256>>>(off, srcs, ssrc, sdst, alpha, den);
    gat_agg_k<2, 64, 7, 1><<<NN / 2, 128>>>(off, srcs, alpha, den, h, b2, g2, bb2,
                                            feat, ssrc, sdst);

    // ---- layer 3: H=1, C=64, HC=64, G=16, NPB=8 ----
    run_gemm(feat, W3, h, 64, 256, a3s, a3d, 1, 6);
    alpha_k<1><<<(NN * 8 + 255) / 256, 256>>>(off, srcs, ssrc, sdst, alpha, den);
    gat_agg_k<1, 16, 6, 0><<<NN / 8, 128>>>(off, srcs, alpha, den, h, b3, g3, bb3,
                                            feat, ssrc, sdst);

    // ---- fused decoder: GEMM+bias+LN+ELU, two launches, no h round-trip ----
    fused_dec_k<<<MB, 256>>>(feat, 64, dW1, db1, lnd1g, lnd1b, h, NN);
    fused_dec_k<<<MB, 256>>>(h, 128, dW2, db2, lnd2g, lnd2b, (float*)d_out, NN);
}